// round 5
// baseline (speedup 1.0000x reference)
#include <cuda_runtime.h>

// ============================================================================
// ModelR: x[8192,1024] -> (Linear+LeakyReLU) x4 -> Linear -> tri-scatter
// Output: [64, 64, 8192] fp32, upper-triangle (c>=r) populated, diag abs'ed.
//
// Round 3 fixes vs R2:
//  1. scatter_tri read was transposed (tile[tyi+i][txi] -> tile[txi][tyi+i]).
//  2. Inputs identified by element count (robust to metadata ordering).
// GEMM unchanged: fp32 SIMT (BM=128,BN=128,BK=16, 8x8/thread), compute-bound.
// ============================================================================

#define BATCH 8192
#define DIN   1024
#define HID   2048
#define LOUT  2080   // 64*65/2
#define CPV   64

#define BM 128
#define BN 128
#define BK 16
#define TM 8
#define TN 8
#define NT 256

// Scratch (allocation-free rule: __device__ globals)
__device__ float g_bufA[(size_t)BATCH * HID];
__device__ float g_bufB[(size_t)BATCH * HID];
__device__ float g_bufY[(size_t)BATCH * LOUT];

// C[M,N] = act(A[M,K] @ W[K,N] + bias[N]);  act=1 -> leaky_relu(0.01)
// Requires M % BM == 0, K % BK == 0, N % 4 == 0 (N guarded vs grid overshoot).
__global__ void __launch_bounds__(NT, 2)
sgemm_bias_act(const float* __restrict__ A, const float* __restrict__ W,
               const float* __restrict__ bias, float* __restrict__ C,
               int M, int N, int K, int act)
{
    __shared__ float As[BK][BM];   // transposed A tile
    __shared__ float Bs[BK][BN];

    const int tid = threadIdx.x;
    const int m0 = blockIdx.y * BM;
    const int n0 = blockIdx.x * BN;

    const int tx = tid & 15;   // 16 col groups of TN
    const int ty = tid >> 4;   // 16 row groups of TM

    float acc[TM][TN];
#pragma unroll
    for (int i = 0; i < TM; i++)
#pragma unroll
        for (int j = 0; j < TN; j++) acc[i][j] = 0.f;

    for (int k0 = 0; k0 < K; k0 += BK) {
        // --- load A tile: 128 rows x 16 cols, float4 along K, store transposed
#pragma unroll
        for (int i = 0; i < 2; i++) {
            int flat = tid + i * NT;              // 0..511
            int ar = flat >> 2;                   // 0..127
            int ak = (flat & 3) << 2;             // 0,4,8,12
            float4 v = *(const float4*)(A + (size_t)(m0 + ar) * K + k0 + ak);
            As[ak + 0][ar] = v.x;
            As[ak + 1][ar] = v.y;
            As[ak + 2][ar] = v.z;
            As[ak + 3][ar] = v.w;
        }
        // --- load W tile: 16 rows x 128 cols, float4 along N (guarded)
#pragma unroll
        for (int i = 0; i < 2; i++) {
            int flat = tid + i * NT;              // 0..511
            int bk = flat >> 5;                   // 0..15
            int bc = (flat & 31) << 2;            // 0..124
            float4 v = make_float4(0.f, 0.f, 0.f, 0.f);
            int n = n0 + bc;
            if (n < N)
                v = *(const float4*)(W + (size_t)(k0 + bk) * N + n);
            *(float4*)&Bs[bk][bc] = v;
        }
        __syncthreads();

#pragma unroll
        for (int kk = 0; kk < BK; kk++) {
            float a[TM], b[TN];
            *(float4*)&a[0] = *(const float4*)&As[kk][ty * TM];
            *(float4*)&a[4] = *(const float4*)&As[kk][ty * TM + 4];
            *(float4*)&b[0] = *(const float4*)&Bs[kk][tx * TN];
            *(float4*)&b[4] = *(const float4*)&Bs[kk][tx * TN + 4];
#pragma unroll
            for (int i = 0; i < TM; i++)
#pragma unroll
                for (int j = 0; j < TN; j++)
                    acc[i][j] = fmaf(a[i], b[j], acc[i][j]);
        }
        __syncthreads();
    }

    // --- epilogue: bias + optional leaky relu, guarded float4 stores
#pragma unroll
    for (int i = 0; i < TM; i++) {
        int m = m0 + ty * TM + i;
#pragma unroll
        for (int j = 0; j < TN; j += 4) {
            int n = n0 + tx * TN + j;
            if (n < N) {
                float4 v;
                v.x = acc[i][j + 0] + __ldg(bias + n + 0);
                v.y = acc[i][j + 1] + __ldg(bias + n + 1);
                v.z = acc[i][j + 2] + __ldg(bias + n + 2);
                v.w = acc[i][j + 3] + __ldg(bias + n + 3);
                if (act) {
                    v.x = v.x > 0.f ? v.x : 0.01f * v.x;
                    v.y = v.y > 0.f ? v.y : 0.01f * v.y;
                    v.z = v.z > 0.f ? v.z : 0.01f * v.z;
                    v.w = v.w > 0.f ? v.w : 0.01f * v.w;
                }
                *(float4*)(C + (size_t)m * N + n) = v;
            }
        }
    }
}

// Transpose-scatter: y[B, LOUT] -> out[(r*64+c)*BATCH + b], diag abs.
// tile is loaded [batch_local][l_local]; write phase reads the TRANSPOSED
// element tile[txi][tyi+i]  (R2 bug: read tile[tyi+i][txi]).
// Lower triangle pre-zeroed by memset. Coalesced load and store.
__global__ void scatter_tri(const float* __restrict__ y, float* __restrict__ out)
{
    __shared__ float tile[32][33];
    const int l0 = blockIdx.x * 32;
    const int b0 = blockIdx.y * 32;
    const int txi = threadIdx.x;
    const int tyi = threadIdx.y;

#pragma unroll
    for (int i = 0; i < 32; i += 8)
        tile[tyi + i][txi] = y[(size_t)(b0 + tyi + i) * LOUT + l0 + txi];
    __syncthreads();

#pragma unroll
    for (int i = 0; i < 32; i += 8) {
        int l = l0 + tyi + i;
        // invert flat index l -> (r, c): row r starts at S(r) = r*(129-r)/2,
        // c = 63 - (l - S(r))
        float disc = 16641.0f - 8.0f * (float)l;
        int r = (int)((129.0f - sqrtf(disc)) * 0.5f);
        if (r < 0) r = 0;
        if (r > 63) r = 63;
        while (r < 63 && (r + 1) * (129 - (r + 1)) / 2 <= l) r++;
        while (r > 0 && r * (129 - r) / 2 > l) r--;
        int c = 63 - (l - r * (129 - r) / 2);
        float v = tile[txi][tyi + i];           // FIXED: transposed read
        if (r == c && v <= 0.f) v = -v;
        out[((size_t)(r * CPV + c)) * BATCH + b0 + txi] = v;
    }
}

extern "C" void kernel_launch(void* const* d_in, const int* in_sizes, int n_in,
                              void* d_out, int out_size)
{
    // Identify inputs by element count — robust to metadata ordering.
    // Unique sizes: x=8388608, W1=2097152, W3=4259840, b3=2080.
    // Same-size groups (H*H weights, H biases) assigned in encounter order,
    // which is (W2, W21, W22) / (b1, b2, b21, b22) under both dict order and
    // any stable (e.g. alphabetical) sort.
    const float *x = 0, *W1 = 0, *W2 = 0, *W21 = 0, *W22 = 0, *W3 = 0;
    const float *b1 = 0, *b2 = 0, *b21 = 0, *b22 = 0, *b3 = 0;
    int nhh = 0, nbb = 0;
    for (int i = 0; i < n_in; i++) {
        const float* p = (const float*)d_in[i];
        switch (in_sizes[i]) {
            case 8388608: x  = p; break;                       // 8192*1024
            case 2097152: W1 = p; break;                       // 1024*2048
            case 4259840: W3 = p; break;                       // 2048*2080
            case 2080:    b3 = p; break;
            case 4194304:                                      // 2048*2048
                if      (nhh == 0) W2  = p;
                else if (nhh == 1) W21 = p;
                else               W22 = p;
                nhh++; break;
            case 2048:
                if      (nbb == 0) b1  = p;
                else if (nbb == 1) b2  = p;
                else if (nbb == 2) b21 = p;
                else               b22 = p;
                nbb++; break;
            default: break;
        }
    }

    void *pA = nullptr, *pB = nullptr, *pY = nullptr;
    cudaGetSymbolAddress(&pA, g_bufA);
    cudaGetSymbolAddress(&pB, g_bufB);
    cudaGetSymbolAddress(&pY, g_bufY);
    float* bufA = (float*)pA;
    float* bufB = (float*)pB;
    float* bufY = (float*)pY;

    dim3 blk(NT);
    dim3 gH(HID / BN, BATCH / BM);              // (16, 64)
    dim3 gL((LOUT + BN - 1) / BN, BATCH / BM);  // (17, 64)

    sgemm_bias_act<<<gH, blk>>>(x,    W1,  b1,  bufA, BATCH, HID,  DIN, 1);
    sgemm_bias_act<<<gH, blk>>>(bufA, W2,  b2,  bufB, BATCH, HID,  HID, 1);
    sgemm_bias_act<<<gH, blk>>>(bufB, W21, b21, bufA, BATCH, HID,  HID, 1);
    sgemm_bias_act<<<gH, blk>>>(bufA, W22, b22, bufB, BATCH, HID,  HID, 1);
    sgemm_bias_act<<<gL, blk>>>(bufB, W3,  b3,  bufY, BATCH, LOUT, HID, 0);

    cudaMemsetAsync(d_out, 0, (size_t)out_size * sizeof(float), 0);

    dim3 gsc(LOUT / 32, BATCH / 32);  // (65, 256)
    dim3 bsc(32, 8);
    scatter_tri<<<gsc, bsc>>>(bufY, (float*)d_out);
}

// round 7
// speedup vs baseline: 2.4473x; 2.4473x over previous
#include <cuda_runtime.h>
#include <cuda_bf16.h>
#include <cstdint>

// ============================================================================
// ModelR: x[8192,1024] -> (Linear+LeakyReLU) x4 -> Linear -> tri-scatter
// Round 7: tensor cores via family-portable mma.sync (HMMA) — tcgen05 is
// rejected by this harness's compute_103 virtual arch.
//   D = Ah*Bh + Ah*Bl + Al*Bh  (bf16 hi/lo split, fp32 accum, err ~2^-16)
//   Tiles: BM=128, BN=128, BK=32, 8 warps (warp tile 64x32), 3-stage cp.async.
//   smem rows padded to 80B pitch -> conflict-free ldmatrix + cp.async.
// ============================================================================

#define BATCH 8192
#define DIN   1024
#define HID   2048
#define LOUT  2080
#define CPV   64

#define PITCH   80          // 64B of data (32 bf16) + 16B pad
#define OFF_AH  0
#define OFF_AL  10240       // 128 rows * 80B
#define OFF_BH  20480
#define OFF_BL  30720
#define STAGE   40960
#define NSTAGE  3
#define SMEMSZ  (NSTAGE * STAGE)   // 122880 B

// ------------------------- device scratch (no allocs) -----------------------
__device__ __nv_bfloat16 g_Ah0[(size_t)BATCH * HID];
__device__ __nv_bfloat16 g_Al0[(size_t)BATCH * HID];
__device__ __nv_bfloat16 g_Ah1[(size_t)BATCH * HID];
__device__ __nv_bfloat16 g_Al1[(size_t)BATCH * HID];
__device__ __nv_bfloat16 g_W1h[(size_t)HID * DIN];
__device__ __nv_bfloat16 g_W1l[(size_t)HID * DIN];
__device__ __nv_bfloat16 g_W2h[(size_t)HID * HID];
__device__ __nv_bfloat16 g_W2l[(size_t)HID * HID];
__device__ __nv_bfloat16 g_W21h[(size_t)HID * HID];
__device__ __nv_bfloat16 g_W21l[(size_t)HID * HID];
__device__ __nv_bfloat16 g_W22h[(size_t)HID * HID];
__device__ __nv_bfloat16 g_W22l[(size_t)HID * HID];
__device__ __nv_bfloat16 g_W3h[(size_t)LOUT * HID];
__device__ __nv_bfloat16 g_W3l[(size_t)LOUT * HID];
__device__ float         g_Y[(size_t)BATCH * LOUT];

// ------------------------------ PTX helpers ---------------------------------
__device__ __forceinline__ uint32_t smem_u32(const void* p) {
    uint32_t a;
    asm("{ .reg .u64 t; cvta.to.shared.u64 t, %1; cvt.u32.u64 %0, t; }"
        : "=r"(a) : "l"(p));
    return a;
}
__device__ __forceinline__ void cp16(uint32_t d, const void* s, int sz) {
    asm volatile("cp.async.cg.shared.global [%0], [%1], 16, %2;"
                 :: "r"(d), "l"(s), "r"(sz) : "memory");
}
__device__ __forceinline__ void cp_commit() {
    asm volatile("cp.async.commit_group;" ::: "memory");
}
template <int N> __device__ __forceinline__ void cp_wait() {
    asm volatile("cp.async.wait_group %0;" :: "n"(N) : "memory");
}
__device__ __forceinline__ void ldsm4(uint32_t* r, uint32_t a) {
    asm volatile("ldmatrix.sync.aligned.m8n8.x4.shared.b16 {%0,%1,%2,%3}, [%4];"
                 : "=r"(r[0]), "=r"(r[1]), "=r"(r[2]), "=r"(r[3]) : "r"(a));
}
__device__ __forceinline__ void mma16816(float* d, const uint32_t* a,
                                         const uint32_t* b) {
    asm volatile(
        "mma.sync.aligned.m16n8k16.row.col.f32.bf16.bf16.f32 "
        "{%0,%1,%2,%3}, {%4,%5,%6,%7}, {%8,%9}, {%0,%1,%2,%3};"
        : "+f"(d[0]), "+f"(d[1]), "+f"(d[2]), "+f"(d[3])
        : "r"(a[0]), "r"(a[1]), "r"(a[2]), "r"(a[3]), "r"(b[0]), "r"(b[1]));
}

// ------------------------------- GEMM kernel --------------------------------
// D[M, Ntot] = split3(A[M,K]) @ split3(B[Ntot,K])^T + bias; optional lrelu.
// Output: bf16 hi/lo split (next layer) or fp32 Y.
__global__ void __launch_bounds__(256, 1)
gemm_bf16x3(const __nv_bfloat16* __restrict__ Ahi, const __nv_bfloat16* __restrict__ Alo,
            const __nv_bfloat16* __restrict__ Bhi, const __nv_bfloat16* __restrict__ Blo,
            const float* __restrict__ bias,
            __nv_bfloat16* __restrict__ Chi, __nv_bfloat16* __restrict__ Clo,
            float* __restrict__ Yout,
            int K, int Ntot, int act, int f32out)
{
    extern __shared__ char sm[];
    const uint32_t sbase = smem_u32(sm);

    const int tid  = threadIdx.x;
    const int wid  = tid >> 5;
    const int lane = tid & 31;
    const int warp_m = wid & 1;        // 2 x 64 rows
    const int warp_n = wid >> 1;       // 4 x 32 cols
    const int m0 = blockIdx.y * 128;
    const int n0 = blockIdx.x * 128;

    float acc[4][4][4];
#pragma unroll
    for (int i = 0; i < 4; i++)
#pragma unroll
        for (int j = 0; j < 4; j++)
#pragma unroll
            for (int k = 0; k < 4; k++) acc[i][j][k] = 0.f;

    // cp.async mapping: 256 threads, each loads rows (t/4) and (t/4)+64,
    // 16B chunk (t%4) of the 64B row, for each of the 4 tiles (Ah/Al/Bh/Bl).
    const int c_row = tid >> 2;
    const int c_col = tid & 3;
    const int kn = K >> 5;             // BK = 32

    // ldmatrix per-lane offsets (bytes, within a stage)
    const uint32_t a_off = (uint32_t)((warp_m * 64 + (lane & 15)) * PITCH
                                      + (lane >> 4) * 16);
    const uint32_t b_off = (uint32_t)((warp_n * 32 + (lane & 7) + ((lane >> 4) << 3)) * PITCH
                                      + ((lane >> 3) & 1) * 16);

#define LOAD_STAGE(KS, BUF)                                                          \
    {                                                                                \
        const int k0_ = (KS) << 5;                                                   \
        const uint32_t sb_ = sbase + (BUF) * STAGE;                                  \
        _Pragma("unroll")                                                            \
        for (int h_ = 0; h_ < 2; h_++) {                                             \
            int row_ = c_row + h_ * 64;                                              \
            uint32_t d_ = sb_ + (uint32_t)(row_ * PITCH + c_col * 16);               \
            size_t ga_ = (size_t)(m0 + row_) * K + k0_ + c_col * 8;                  \
            cp16(d_ + OFF_AH, Ahi + ga_, 16);                                        \
            cp16(d_ + OFF_AL, Alo + ga_, 16);                                        \
            int n_ = n0 + row_;                                                      \
            int sz_ = (n_ < Ntot) ? 16 : 0;                                          \
            int nc_ = (n_ < Ntot) ? n_ : (Ntot - 1);                                 \
            size_t gb_ = (size_t)nc_ * K + k0_ + c_col * 8;                          \
            cp16(d_ + OFF_BH, Bhi + gb_, sz_);                                       \
            cp16(d_ + OFF_BL, Blo + gb_, sz_);                                       \
        }                                                                            \
    }

    // prologue: stages 0, 1
    LOAD_STAGE(0, 0); cp_commit();
    if (kn > 1) { LOAD_STAGE(1, 1); cp_commit(); }

    for (int ks = 0; ks < kn; ks++) {
        const int buf = ks % 3;
        if (ks + 2 < kn) {
            LOAD_STAGE(ks + 2, (ks + 2) % 3); cp_commit(); cp_wait<2>();
        } else if (ks + 1 < kn) {
            cp_wait<1>();
        } else {
            cp_wait<0>();
        }
        __syncthreads();

        const uint32_t sb = sbase + buf * STAGE;
#pragma unroll
        for (int kk = 0; kk < 2; kk++) {
            uint32_t ah[4][4], al[4][4], bh[4][2], bl[4][2];
#pragma unroll
            for (int mt = 0; mt < 4; mt++) {
                uint32_t o = a_off + (uint32_t)(mt * 16 * PITCH + kk * 32);
                ldsm4(ah[mt], sb + OFF_AH + o);
                ldsm4(al[mt], sb + OFF_AL + o);
            }
#pragma unroll
            for (int np = 0; np < 2; np++) {
                uint32_t o = b_off + (uint32_t)(np * 16 * PITCH + kk * 32);
                uint32_t r[4];
                ldsm4(r, sb + OFF_BH + o);
                bh[2 * np][0] = r[0]; bh[2 * np][1] = r[1];
                bh[2 * np + 1][0] = r[2]; bh[2 * np + 1][1] = r[3];
                ldsm4(r, sb + OFF_BL + o);
                bl[2 * np][0] = r[0]; bl[2 * np][1] = r[1];
                bl[2 * np + 1][0] = r[2]; bl[2 * np + 1][1] = r[3];
            }
#pragma unroll
            for (int mt = 0; mt < 4; mt++)
#pragma unroll
                for (int nt = 0; nt < 4; nt++) {
                    mma16816(acc[mt][nt], ah[mt], bh[nt]);
                    mma16816(acc[mt][nt], ah[mt], bl[nt]);
                    mma16816(acc[mt][nt], al[mt], bh[nt]);
                }
        }
        __syncthreads();
    }

    // ---- epilogue: bias + act, write split-bf16 or fp32 ----
    const int mrow = lane >> 2;
    const int ncol = (lane & 3) * 2;
#pragma unroll
    for (int mt = 0; mt < 4; mt++) {
#pragma unroll
        for (int nt = 0; nt < 4; nt++) {
            int n = n0 + warp_n * 32 + nt * 8 + ncol;
            if (n >= Ntot) continue;
            float bs0 = __ldg(bias + n);
            float bs1 = __ldg(bias + n + 1);
#pragma unroll
            for (int half = 0; half < 2; half++) {
                int m = m0 + warp_m * 64 + mt * 16 + mrow + half * 8;
                float v0 = acc[mt][nt][half * 2]     + bs0;
                float v1 = acc[mt][nt][half * 2 + 1] + bs1;
                if (act) {
                    v0 = v0 > 0.f ? v0 : 0.01f * v0;
                    v1 = v1 > 0.f ? v1 : 0.01f * v1;
                }
                if (f32out) {
                    *(float2*)(Yout + (size_t)m * Ntot + n) = make_float2(v0, v1);
                } else {
                    __nv_bfloat16 h0 = __float2bfloat16(v0);
                    __nv_bfloat16 h1 = __float2bfloat16(v1);
                    __nv_bfloat16 l0 = __float2bfloat16(v0 - __bfloat162float(h0));
                    __nv_bfloat16 l1 = __float2bfloat16(v1 - __bfloat162float(h1));
                    *(__nv_bfloat162*)(Chi + (size_t)m * Ntot + n) = __halves2bfloat162(h0, h1);
                    *(__nv_bfloat162*)(Clo + (size_t)m * Ntot + n) = __halves2bfloat162(l0, l1);
                }
            }
        }
    }
}

// --------------------------- split / transpose ------------------------------
__global__ void split_f32_kernel(const float* __restrict__ in,
                                 __nv_bfloat16* __restrict__ hi,
                                 __nv_bfloat16* __restrict__ lo, int n4)
{
    int i = blockIdx.x * blockDim.x + threadIdx.x;
    if (i < n4) {
        float4 v = ((const float4*)in)[i];
        __nv_bfloat16 h0 = __float2bfloat16(v.x), h1 = __float2bfloat16(v.y);
        __nv_bfloat16 h2 = __float2bfloat16(v.z), h3 = __float2bfloat16(v.w);
        __nv_bfloat16 l0 = __float2bfloat16(v.x - __bfloat162float(h0));
        __nv_bfloat16 l1 = __float2bfloat16(v.y - __bfloat162float(h1));
        __nv_bfloat16 l2 = __float2bfloat16(v.z - __bfloat162float(h2));
        __nv_bfloat16 l3 = __float2bfloat16(v.w - __bfloat162float(h3));
        ((__nv_bfloat162*)hi)[i * 2]     = __halves2bfloat162(h0, h1);
        ((__nv_bfloat162*)hi)[i * 2 + 1] = __halves2bfloat162(h2, h3);
        ((__nv_bfloat162*)lo)[i * 2]     = __halves2bfloat162(l0, l1);
        ((__nv_bfloat162*)lo)[i * 2 + 1] = __halves2bfloat162(l2, l3);
    }
}

// W[K,N] fp32 -> BT[N,K] bf16 hi/lo (transpose + split). Dims %32 == 0.
__global__ void wsplit_t_kernel(const float* __restrict__ W,
                                __nv_bfloat16* __restrict__ bth,
                                __nv_bfloat16* __restrict__ btl, int K, int N)
{
    __shared__ float t[32][33];
    const int n0 = blockIdx.x * 32, k0 = blockIdx.y * 32;
    const int tx = threadIdx.x, ty = threadIdx.y;
#pragma unroll
    for (int i = 0; i < 32; i += 8)
        t[ty + i][tx] = W[(size_t)(k0 + ty + i) * N + n0 + tx];
    __syncthreads();
#pragma unroll
    for (int i = 0; i < 32; i += 8) {
        float v = t[tx][ty + i];                 // element (k0+tx, n0+ty+i)
        __nv_bfloat16 h = __float2bfloat16(v);
        __nv_bfloat16 l = __float2bfloat16(v - __bfloat162float(h));
        size_t o = (size_t)(n0 + ty + i) * K + k0 + tx;
        bth[o] = h;
        btl[o] = l;
    }
}

// ------------------------------- scatter ------------------------------------
__global__ void scatter_tri(const float* __restrict__ y, float* __restrict__ out)
{
    __shared__ float tile[32][33];
    const int l0 = blockIdx.x * 32;
    const int b0 = blockIdx.y * 32;
    const int txi = threadIdx.x;
    const int tyi = threadIdx.y;

#pragma unroll
    for (int i = 0; i < 32; i += 8)
        tile[tyi + i][txi] = y[(size_t)(b0 + tyi + i) * LOUT + l0 + txi];
    __syncthreads();

#pragma unroll
    for (int i = 0; i < 32; i += 8) {
        int l = l0 + tyi + i;
        float disc = 16641.0f - 8.0f * (float)l;
        int r = (int)((129.0f - sqrtf(disc)) * 0.5f);
        if (r < 0) r = 0;
        if (r > 63) r = 63;
        while (r < 63 && (r + 1) * (129 - (r + 1)) / 2 <= l) r++;
        while (r > 0 && r * (129 - r) / 2 > l) r--;
        int c = 63 - (l - r * (129 - r) / 2);
        float v = tile[txi][tyi + i];            // transposed read
        if (r == c && v <= 0.f) v = -v;
        out[((size_t)(r * CPV + c)) * BATCH + b0 + txi] = v;
    }
}

// ------------------------------- launcher -----------------------------------
extern "C" void kernel_launch(void* const* d_in, const int* in_sizes, int n_in,
                              void* d_out, int out_size)
{
    // Identify inputs by element count (robust to metadata ordering).
    const float *x = 0, *W1 = 0, *W2 = 0, *W21 = 0, *W22 = 0, *W3 = 0;
    const float *b1 = 0, *b2 = 0, *b21 = 0, *b22 = 0, *b3 = 0;
    int nhh = 0, nbb = 0;
    for (int i = 0; i < n_in; i++) {
        const float* p = (const float*)d_in[i];
        switch (in_sizes[i]) {
            case 8388608: x  = p; break;
            case 2097152: W1 = p; break;
            case 4259840: W3 = p; break;
            case 2080:    b3 = p; break;
            case 4194304:
                if      (nhh == 0) W2  = p;
                else if (nhh == 1) W21 = p;
                else               W22 = p;
                nhh++; break;
            case 2048:
                if      (nbb == 0) b1  = p;
                else if (nbb == 1) b2  = p;
                else if (nbb == 2) b21 = p;
                else               b22 = p;
                nbb++; break;
            default: break;
        }
    }

    void *pAh0, *pAl0, *pAh1, *pAl1, *pW1h, *pW1l, *pW2h, *pW2l;
    void *pW21h, *pW21l, *pW22h, *pW22l, *pW3h, *pW3l, *pY;
    cudaGetSymbolAddress(&pAh0, g_Ah0);   cudaGetSymbolAddress(&pAl0, g_Al0);
    cudaGetSymbolAddress(&pAh1, g_Ah1);   cudaGetSymbolAddress(&pAl1, g_Al1);
    cudaGetSymbolAddress(&pW1h, g_W1h);   cudaGetSymbolAddress(&pW1l, g_W1l);
    cudaGetSymbolAddress(&pW2h, g_W2h);   cudaGetSymbolAddress(&pW2l, g_W2l);
    cudaGetSymbolAddress(&pW21h, g_W21h); cudaGetSymbolAddress(&pW21l, g_W21l);
    cudaGetSymbolAddress(&pW22h, g_W22h); cudaGetSymbolAddress(&pW22l, g_W22l);
    cudaGetSymbolAddress(&pW3h, g_W3h);   cudaGetSymbolAddress(&pW3l, g_W3l);
    cudaGetSymbolAddress(&pY, g_Y);
    __nv_bfloat16 *Ah0 = (__nv_bfloat16*)pAh0, *Al0 = (__nv_bfloat16*)pAl0;
    __nv_bfloat16 *Ah1 = (__nv_bfloat16*)pAh1, *Al1 = (__nv_bfloat16*)pAl1;
    __nv_bfloat16 *W1h = (__nv_bfloat16*)pW1h, *W1l = (__nv_bfloat16*)pW1l;
    __nv_bfloat16 *W2h = (__nv_bfloat16*)pW2h, *W2l = (__nv_bfloat16*)pW2l;
    __nv_bfloat16 *W21h = (__nv_bfloat16*)pW21h, *W21l = (__nv_bfloat16*)pW21l;
    __nv_bfloat16 *W22h = (__nv_bfloat16*)pW22h, *W22l = (__nv_bfloat16*)pW22l;
    __nv_bfloat16 *W3h = (__nv_bfloat16*)pW3h, *W3l = (__nv_bfloat16*)pW3l;
    float* Y = (float*)pY;

    cudaFuncSetAttribute(gemm_bf16x3,
                         cudaFuncAttributeMaxDynamicSharedMemorySize, SMEMSZ);

    // Split x; transpose+split weights.
    split_f32_kernel<<<(BATCH * DIN / 4 + 255) / 256, 256>>>(x, Ah0, Al0, BATCH * DIN / 4);
    dim3 tb(32, 8);
    wsplit_t_kernel<<<dim3(HID / 32, DIN / 32), tb>>>(W1, W1h, W1l, DIN, HID);
    wsplit_t_kernel<<<dim3(HID / 32, HID / 32), tb>>>(W2, W2h, W2l, HID, HID);
    wsplit_t_kernel<<<dim3(HID / 32, HID / 32), tb>>>(W21, W21h, W21l, HID, HID);
    wsplit_t_kernel<<<dim3(HID / 32, HID / 32), tb>>>(W22, W22h, W22l, HID, HID);
    wsplit_t_kernel<<<dim3(LOUT / 32, HID / 32), tb>>>(W3, W3h, W3l, HID, LOUT);

    // GEMM chain (HMMA tensor cores)
    dim3 blk(256);
    dim3 gH(HID / 128, BATCH / 128);                     // (16, 64)
    dim3 gL((LOUT + 127) / 128, BATCH / 128);            // (17, 64)
    gemm_bf16x3<<<gH, blk, SMEMSZ>>>(Ah0, Al0, W1h, W1l, b1, Ah1, Al1, 0, DIN, HID, 1, 0);
    gemm_bf16x3<<<gH, blk, SMEMSZ>>>(Ah1, Al1, W2h, W2l, b2, Ah0, Al0, 0, HID, HID, 1, 0);
    gemm_bf16x3<<<gH, blk, SMEMSZ>>>(Ah0, Al0, W21h, W21l, b21, Ah1, Al1, 0, HID, HID, 1, 0);
    gemm_bf16x3<<<gH, blk, SMEMSZ>>>(Ah1, Al1, W22h, W22l, b22, Ah0, Al0, 0, HID, HID, 1, 0);
    gemm_bf16x3<<<gL, blk, SMEMSZ>>>(Ah0, Al0, W3h, W3l, b3, 0, 0, Y, HID, LOUT, 0, 1);

    cudaMemsetAsync(d_out, 0, (size_t)out_size * sizeof(float), 0);
    dim3 gsc(LOUT / 32, BATCH / 32);
    dim3 bsc(32, 8);
    scatter_tri<<<gsc, bsc>>>(Y, (float*)d_out);
}

// round 8
// speedup vs baseline: 2.7811x; 1.1364x over previous
#include <cuda_runtime.h>
#include <cuda_bf16.h>
#include <cstdint>

// ============================================================================
// ModelR: x[8192,1024] -> (Linear+LeakyReLU) x4 -> Linear -> tri-scatter
// Round 8: HMMA bf16 3-term split GEMM; BK 32->64 (half the barrier count,
// 2x MMA work per stage), pitch 144B, 3-stage cp.async (221KB smem, 1 CTA/SM).
//   D = Ah*Bh + Ah*Bl + Al*Bh  (bf16 hi/lo split, fp32 accum, err ~2^-16)
// ============================================================================

#define BATCH 8192
#define DIN   1024
#define HID   2048
#define LOUT  2080
#define CPV   64

#define PITCH   144         // 128B payload (64 bf16) + 16B pad
#define OFF_AH  0
#define OFF_AL  18432       // 128 rows * 144B
#define OFF_BH  36864
#define OFF_BL  55296
#define STAGE   73728
#define NSTAGE  3
#define SMEMSZ  (NSTAGE * STAGE)   // 221184 B

// ------------------------- device scratch (no allocs) -----------------------
__device__ __nv_bfloat16 g_Ah0[(size_t)BATCH * HID];
__device__ __nv_bfloat16 g_Al0[(size_t)BATCH * HID];
__device__ __nv_bfloat16 g_Ah1[(size_t)BATCH * HID];
__device__ __nv_bfloat16 g_Al1[(size_t)BATCH * HID];
__device__ __nv_bfloat16 g_W1h[(size_t)HID * DIN];
__device__ __nv_bfloat16 g_W1l[(size_t)HID * DIN];
__device__ __nv_bfloat16 g_W2h[(size_t)HID * HID];
__device__ __nv_bfloat16 g_W2l[(size_t)HID * HID];
__device__ __nv_bfloat16 g_W21h[(size_t)HID * HID];
__device__ __nv_bfloat16 g_W21l[(size_t)HID * HID];
__device__ __nv_bfloat16 g_W22h[(size_t)HID * HID];
__device__ __nv_bfloat16 g_W22l[(size_t)HID * HID];
__device__ __nv_bfloat16 g_W3h[(size_t)LOUT * HID];
__device__ __nv_bfloat16 g_W3l[(size_t)LOUT * HID];
__device__ float         g_Y[(size_t)BATCH * LOUT];

// ------------------------------ PTX helpers ---------------------------------
__device__ __forceinline__ uint32_t smem_u32(const void* p) {
    uint32_t a;
    asm("{ .reg .u64 t; cvta.to.shared.u64 t, %1; cvt.u32.u64 %0, t; }"
        : "=r"(a) : "l"(p));
    return a;
}
__device__ __forceinline__ void cp16(uint32_t d, const void* s, int sz) {
    asm volatile("cp.async.cg.shared.global [%0], [%1], 16, %2;"
                 :: "r"(d), "l"(s), "r"(sz) : "memory");
}
__device__ __forceinline__ void cp_commit() {
    asm volatile("cp.async.commit_group;" ::: "memory");
}
template <int N> __device__ __forceinline__ void cp_wait() {
    asm volatile("cp.async.wait_group %0;" :: "n"(N) : "memory");
}
__device__ __forceinline__ void ldsm4(uint32_t* r, uint32_t a) {
    asm volatile("ldmatrix.sync.aligned.m8n8.x4.shared.b16 {%0,%1,%2,%3}, [%4];"
                 : "=r"(r[0]), "=r"(r[1]), "=r"(r[2]), "=r"(r[3]) : "r"(a));
}
__device__ __forceinline__ void mma16816(float* d, const uint32_t* a,
                                         const uint32_t* b) {
    asm volatile(
        "mma.sync.aligned.m16n8k16.row.col.f32.bf16.bf16.f32 "
        "{%0,%1,%2,%3}, {%4,%5,%6,%7}, {%8,%9}, {%0,%1,%2,%3};"
        : "+f"(d[0]), "+f"(d[1]), "+f"(d[2]), "+f"(d[3])
        : "r"(a[0]), "r"(a[1]), "r"(a[2]), "r"(a[3]), "r"(b[0]), "r"(b[1]));
}

// ------------------------------- GEMM kernel --------------------------------
// D[M, Ntot] = split3(A[M,K]) @ split3(B[Ntot,K])^T + bias; optional lrelu.
// BM=128, BN=128, BK=64. 8 warps: warp tile 64x32 (warp_m 2 x warp_n 4).
__global__ void __launch_bounds__(256, 1)
gemm_bf16x3(const __nv_bfloat16* __restrict__ Ahi, const __nv_bfloat16* __restrict__ Alo,
            const __nv_bfloat16* __restrict__ Bhi, const __nv_bfloat16* __restrict__ Blo,
            const float* __restrict__ bias,
            __nv_bfloat16* __restrict__ Chi, __nv_bfloat16* __restrict__ Clo,
            float* __restrict__ Yout,
            int K, int Ntot, int act, int f32out)
{
    extern __shared__ char sm[];
    const uint32_t sbase = smem_u32(sm);

    const int tid  = threadIdx.x;
    const int wid  = tid >> 5;
    const int lane = tid & 31;
    const int warp_m = wid & 1;        // 2 x 64 rows
    const int warp_n = wid >> 1;       // 4 x 32 cols
    const int m0 = blockIdx.y * 128;
    const int n0 = blockIdx.x * 128;

    float acc[4][4][4];
#pragma unroll
    for (int i = 0; i < 4; i++)
#pragma unroll
        for (int j = 0; j < 4; j++)
#pragma unroll
            for (int k = 0; k < 4; k++) acc[i][j][k] = 0.f;

    const int kn = K >> 6;             // BK = 64

    // ldmatrix per-lane offsets (bytes, within a stage)
    const uint32_t a_off = (uint32_t)((warp_m * 64 + (lane & 15)) * PITCH
                                      + (lane >> 4) * 16);
    const uint32_t b_off = (uint32_t)((warp_n * 32 + (lane & 7) + ((lane >> 4) << 3)) * PITCH
                                      + ((lane >> 3) & 1) * 16);

    // cp.async: 4 tiles (Ah/Al/Bh/Bl), each 128 rows x 128B = 1024 x 16B chunks;
    // 256 threads -> 4 chunks per thread per tile (16 cp16 total per stage).
#define LOAD_STAGE(KS, BUF)                                                          \
    {                                                                                \
        const int k0_ = (KS) << 6;                                                   \
        const uint32_t sb_ = sbase + (BUF) * STAGE;                                  \
        _Pragma("unroll")                                                            \
        for (int j_ = 0; j_ < 4; j_++) {                                             \
            int slot_ = tid + j_ * 256;                                              \
            int row_ = slot_ >> 3;                                                   \
            int col_ = slot_ & 7;                                                    \
            uint32_t d_ = sb_ + (uint32_t)(row_ * PITCH + col_ * 16);                \
            size_t ga_ = (size_t)(m0 + row_) * K + k0_ + col_ * 8;                   \
            cp16(d_ + OFF_AH, Ahi + ga_, 16);                                        \
            cp16(d_ + OFF_AL, Alo + ga_, 16);                                        \
            int n_ = n0 + row_;                                                      \
            int sz_ = (n_ < Ntot) ? 16 : 0;                                          \
            int nc_ = (n_ < Ntot) ? n_ : (Ntot - 1);                                 \
            size_t gb_ = (size_t)nc_ * K + k0_ + col_ * 8;                           \
            cp16(d_ + OFF_BH, Bhi + gb_, sz_);                                       \
            cp16(d_ + OFF_BL, Blo + gb_, sz_);                                       \
        }                                                                            \
    }

    // prologue: stages 0, 1
    LOAD_STAGE(0, 0); cp_commit();
    if (kn > 1) { LOAD_STAGE(1, 1); cp_commit(); }

    for (int ks = 0; ks < kn; ks++) {
        const int buf = ks % 3;
        if (ks + 2 < kn) {
            LOAD_STAGE(ks + 2, (ks + 2) % 3); cp_commit(); cp_wait<2>();
        } else if (ks + 1 < kn) {
            cp_wait<1>();
        } else {
            cp_wait<0>();
        }
        __syncthreads();

        const uint32_t sb = sbase + buf * STAGE;
#pragma unroll
        for (int kk = 0; kk < 4; kk++) {           // 4 x K16 per stage
            uint32_t ah[4][4], al[4][4], bh[4][2], bl[4][2];
#pragma unroll
            for (int mt = 0; mt < 4; mt++) {
                uint32_t o = a_off + (uint32_t)(mt * 16 * PITCH + kk * 32);
                ldsm4(ah[mt], sb + OFF_AH + o);
                ldsm4(al[mt], sb + OFF_AL + o);
            }
#pragma unroll
            for (int np = 0; np < 2; np++) {
                uint32_t o = b_off + (uint32_t)(np * 16 * PITCH + kk * 32);
                uint32_t r[4];
                ldsm4(r, sb + OFF_BH + o);
                bh[2 * np][0] = r[0]; bh[2 * np][1] = r[1];
                bh[2 * np + 1][0] = r[2]; bh[2 * np + 1][1] = r[3];
                ldsm4(r, sb + OFF_BL + o);
                bl[2 * np][0] = r[0]; bl[2 * np][1] = r[1];
                bl[2 * np + 1][0] = r[2]; bl[2 * np + 1][1] = r[3];
            }
#pragma unroll
            for (int mt = 0; mt < 4; mt++)
#pragma unroll
                for (int nt = 0; nt < 4; nt++) {
                    mma16816(acc[mt][nt], ah[mt], bh[nt]);
                    mma16816(acc[mt][nt], ah[mt], bl[nt]);
                    mma16816(acc[mt][nt], al[mt], bh[nt]);
                }
        }
        __syncthreads();
    }

    // ---- epilogue: bias + act, write split-bf16 or fp32 ----
    const int mrow = lane >> 2;
    const int ncol = (lane & 3) * 2;
#pragma unroll
    for (int mt = 0; mt < 4; mt++) {
#pragma unroll
        for (int nt = 0; nt < 4; nt++) {
            int n = n0 + warp_n * 32 + nt * 8 + ncol;
            if (n >= Ntot) continue;
            float bs0 = __ldg(bias + n);
            float bs1 = __ldg(bias + n + 1);
#pragma unroll
            for (int half = 0; half < 2; half++) {
                int m = m0 + warp_m * 64 + mt * 16 + mrow + half * 8;
                float v0 = acc[mt][nt][half * 2]     + bs0;
                float v1 = acc[mt][nt][half * 2 + 1] + bs1;
                if (act) {
                    v0 = v0 > 0.f ? v0 : 0.01f * v0;
                    v1 = v1 > 0.f ? v1 : 0.01f * v1;
                }
                if (f32out) {
                    *(float2*)(Yout + (size_t)m * Ntot + n) = make_float2(v0, v1);
                } else {
                    __nv_bfloat16 h0 = __float2bfloat16(v0);
                    __nv_bfloat16 h1 = __float2bfloat16(v1);
                    __nv_bfloat16 l0 = __float2bfloat16(v0 - __bfloat162float(h0));
                    __nv_bfloat16 l1 = __float2bfloat16(v1 - __bfloat162float(h1));
                    *(__nv_bfloat162*)(Chi + (size_t)m * Ntot + n) = __halves2bfloat162(h0, h1);
                    *(__nv_bfloat162*)(Clo + (size_t)m * Ntot + n) = __halves2bfloat162(l0, l1);
                }
            }
        }
    }
}

// --------------------------- split / transpose ------------------------------
__global__ void split_f32_kernel(const float* __restrict__ in,
                                 __nv_bfloat16* __restrict__ hi,
                                 __nv_bfloat16* __restrict__ lo, int n4)
{
    int i = blockIdx.x * blockDim.x + threadIdx.x;
    if (i < n4) {
        float4 v = ((const float4*)in)[i];
        __nv_bfloat16 h0 = __float2bfloat16(v.x), h1 = __float2bfloat16(v.y);
        __nv_bfloat16 h2 = __float2bfloat16(v.z), h3 = __float2bfloat16(v.w);
        __nv_bfloat16 l0 = __float2bfloat16(v.x - __bfloat162float(h0));
        __nv_bfloat16 l1 = __float2bfloat16(v.y - __bfloat162float(h1));
        __nv_bfloat16 l2 = __float2bfloat16(v.z - __bfloat162float(h2));
        __nv_bfloat16 l3 = __float2bfloat16(v.w - __bfloat162float(h3));
        ((__nv_bfloat162*)hi)[i * 2]     = __halves2bfloat162(h0, h1);
        ((__nv_bfloat162*)hi)[i * 2 + 1] = __halves2bfloat162(h2, h3);
        ((__nv_bfloat162*)lo)[i * 2]     = __halves2bfloat162(l0, l1);
        ((__nv_bfloat162*)lo)[i * 2 + 1] = __halves2bfloat162(l2, l3);
    }
}

// W[K,N] fp32 -> BT[N,K] bf16 hi/lo (transpose + split). Dims %32 == 0.
__global__ void wsplit_t_kernel(const float* __restrict__ W,
                                __nv_bfloat16* __restrict__ bth,
                                __nv_bfloat16* __restrict__ btl, int K, int N)
{
    __shared__ float t[32][33];
    const int n0 = blockIdx.x * 32, k0 = blockIdx.y * 32;
    const int tx = threadIdx.x, ty = threadIdx.y;
#pragma unroll
    for (int i = 0; i < 32; i += 8)
        t[ty + i][tx] = W[(size_t)(k0 + ty + i) * N + n0 + tx];
    __syncthreads();
#pragma unroll
    for (int i = 0; i < 32; i += 8) {
        float v = t[tx][ty + i];                 // element (k0+tx, n0+ty+i)
        __nv_bfloat16 h = __float2bfloat16(v);
        __nv_bfloat16 l = __float2bfloat16(v - __bfloat162float(h));
        size_t o = (size_t)(n0 + ty + i) * K + k0 + tx;
        bth[o] = h;
        btl[o] = l;
    }
}

// ------------------------------- scatter ------------------------------------
__global__ void scatter_tri(const float* __restrict__ y, float* __restrict__ out)
{
    __shared__ float tile[32][33];
    const int l0 = blockIdx.x * 32;
    const int b0 = blockIdx.y * 32;
    const int txi = threadIdx.x;
    const int tyi = threadIdx.y;

#pragma unroll
    for (int i = 0; i < 32; i += 8)
        tile[tyi + i][txi] = y[(size_t)(b0 + tyi + i) * LOUT + l0 + txi];
    __syncthreads();

#pragma unroll
    for (int i = 0; i < 32; i += 8) {
        int l = l0 + tyi + i;
        float disc = 16641.0f - 8.0f * (float)l;
        int r = (int)((129.0f - sqrtf(disc)) * 0.5f);
        if (r < 0) r = 0;
        if (r > 63) r = 63;
        while (r < 63 && (r + 1) * (129 - (r + 1)) / 2 <= l) r++;
        while (r > 0 && r * (129 - r) / 2 > l) r--;
        int c = 63 - (l - r * (129 - r) / 2);
        float v = tile[txi][tyi + i];            // transposed read
        if (r == c && v <= 0.f) v = -v;
        out[((size_t)(r * CPV + c)) * BATCH + b0 + txi] = v;
    }
}

// ------------------------------- launcher -----------------------------------
extern "C" void kernel_launch(void* const* d_in, const int* in_sizes, int n_in,
                              void* d_out, int out_size)
{
    // Identify inputs by element count (robust to metadata ordering).
    const float *x = 0, *W1 = 0, *W2 = 0, *W21 = 0, *W22 = 0, *W3 = 0;
    const float *b1 = 0, *b2 = 0, *b21 = 0, *b22 = 0, *b3 = 0;
    int nhh = 0, nbb = 0;
    for (int i = 0; i < n_in; i++) {
        const float* p = (const float*)d_in[i];
        switch (in_sizes[i]) {
            case 8388608: x  = p; break;
            case 2097152: W1 = p; break;
            case 4259840: W3 = p; break;
            case 2080:    b3 = p; break;
            case 4194304:
                if      (nhh == 0) W2  = p;
                else if (nhh == 1) W21 = p;
                else               W22 = p;
                nhh++; break;
            case 2048:
                if      (nbb == 0) b1  = p;
                else if (nbb == 1) b2  = p;
                else if (nbb == 2) b21 = p;
                else               b22 = p;
                nbb++; break;
            default: break;
        }
    }

    void *pAh0, *pAl0, *pAh1, *pAl1, *pW1h, *pW1l, *pW2h, *pW2l;
    void *pW21h, *pW21l, *pW22h, *pW22l, *pW3h, *pW3l, *pY;
    cudaGetSymbolAddress(&pAh0, g_Ah0);   cudaGetSymbolAddress(&pAl0, g_Al0);
    cudaGetSymbolAddress(&pAh1, g_Ah1);   cudaGetSymbolAddress(&pAl1, g_Al1);
    cudaGetSymbolAddress(&pW1h, g_W1h);   cudaGetSymbolAddress(&pW1l, g_W1l);
    cudaGetSymbolAddress(&pW2h, g_W2h);   cudaGetSymbolAddress(&pW2l, g_W2l);
    cudaGetSymbolAddress(&pW21h, g_W21h); cudaGetSymbolAddress(&pW21l, g_W21l);
    cudaGetSymbolAddress(&pW22h, g_W22h); cudaGetSymbolAddress(&pW22l, g_W22l);
    cudaGetSymbolAddress(&pW3h, g_W3h);   cudaGetSymbolAddress(&pW3l, g_W3l);
    cudaGetSymbolAddress(&pY, g_Y);
    __nv_bfloat16 *Ah0 = (__nv_bfloat16*)pAh0, *Al0 = (__nv_bfloat16*)pAl0;
    __nv_bfloat16 *Ah1 = (__nv_bfloat16*)pAh1, *Al1 = (__nv_bfloat16*)pAl1;
    __nv_bfloat16 *W1h = (__nv_bfloat16*)pW1h, *W1l = (__nv_bfloat16*)pW1l;
    __nv_bfloat16 *W2h = (__nv_bfloat16*)pW2h, *W2l = (__nv_bfloat16*)pW2l;
    __nv_bfloat16 *W21h = (__nv_bfloat16*)pW21h, *W21l = (__nv_bfloat16*)pW21l;
    __nv_bfloat16 *W22h = (__nv_bfloat16*)pW22h, *W22l = (__nv_bfloat16*)pW22l;
    __nv_bfloat16 *W3h = (__nv_bfloat16*)pW3h, *W3l = (__nv_bfloat16*)pW3l;
    float* Y = (float*)pY;

    cudaFuncSetAttribute(gemm_bf16x3,
                         cudaFuncAttributeMaxDynamicSharedMemorySize, SMEMSZ);

    // Split x; transpose+split weights.
    split_f32_kernel<<<(BATCH * DIN / 4 + 255) / 256, 256>>>(x, Ah0, Al0, BATCH * DIN / 4);
    dim3 tb(32, 8);
    wsplit_t_kernel<<<dim3(HID / 32, DIN / 32), tb>>>(W1, W1h, W1l, DIN, HID);
    wsplit_t_kernel<<<dim3(HID / 32, HID / 32), tb>>>(W2, W2h, W2l, HID, HID);
    wsplit_t_kernel<<<dim3(HID / 32, HID / 32), tb>>>(W21, W21h, W21l, HID, HID);
    wsplit_t_kernel<<<dim3(HID / 32, HID / 32), tb>>>(W22, W22h, W22l, HID, HID);
    wsplit_t_kernel<<<dim3(LOUT / 32, HID / 32), tb>>>(W3, W3h, W3l, HID, LOUT);

    // GEMM chain (HMMA tensor cores)
    dim3 blk(256);
    dim3 gH(HID / 128, BATCH / 128);                     // (16, 64)
    dim3 gL((LOUT + 127) / 128, BATCH / 128);            // (17, 64)
    gemm_bf16x3<<<gH, blk, SMEMSZ>>>(Ah0, Al0, W1h, W1l, b1, Ah1, Al1, 0, DIN, HID, 1, 0);
    gemm_bf16x3<<<gH, blk, SMEMSZ>>>(Ah1, Al1, W2h, W2l, b2, Ah0, Al0, 0, HID, HID, 1, 0);
    gemm_bf16x3<<<gH, blk, SMEMSZ>>>(Ah0, Al0, W21h, W21l, b21, Ah1, Al1, 0, HID, HID, 1, 0);
    gemm_bf16x3<<<gH, blk, SMEMSZ>>>(Ah1, Al1, W22h, W22l, b22, Ah0, Al0, 0, HID, HID, 1, 0);
    gemm_bf16x3<<<gL, blk, SMEMSZ>>>(Ah0, Al0, W3h, W3l, b3, 0, 0, Y, HID, LOUT, 0, 1);

    cudaMemsetAsync(d_out, 0, (size_t)out_size * sizeof(float), 0);
    dim3 gsc(LOUT / 32, BATCH / 32);
    dim3 bsc(32, 8);
    scatter_tri<<<gsc, bsc>>>(Y, (float*)d_out);
}